// round 1
// baseline (speedup 1.0000x reference)
#include <cuda_runtime.h>
#include <math.h>

#define NN   10000
#define EE   320000
#define HIDD 128
#define NH   4
#define NL   2
#define NEG  0.2f
#define BNEPS 1e-5f

// ---------------- scratch (device globals; no allocation allowed) ----------------
__device__ float g_h[NN * HIDD];            // node features between layers
__device__ float g_xh[NN * HIDD * NH];      // h @ W[l]  -> [N, H*HID]
__device__ float g_outp[NN * HIDD];         // pre-batchnorm layer output
__device__ float g_ae[EE * 8];              // per-edge attention logits, [E][L][H]
__device__ float g_aeloop[NN * 8];          // self-loop logits, [N][L][H]
__device__ float g_asrc[NN * NH];
__device__ float g_adst[NN * NH];
__device__ int   g_deg[NN];
__device__ int   g_rowptr[NN + 1];
__device__ int   g_fill[NN];
__device__ int   g_col[EE];                 // CSR by dst: edge ids
__device__ float g_ve[NL * HIDD * NH];      // We[l] . att_edge[l,h]   [L][128][H]
__device__ float g_ue[NL * 64 * NH];        // eenc_W @ ve             [L][64][H]
__device__ float g_ce[NL * NH];             // eenc_b . ve
__device__ float g_bnsum[HIDD];
__device__ float g_bnsq[HIDD];

// ---------------- init ----------------
__global__ void k_zero_counts() {
    int i = blockIdx.x * blockDim.x + threadIdx.x;
    if (i < NN) { g_deg[i] = 0; g_fill[i] = 0; }
}

__global__ void k_bnzero() {
    int i = threadIdx.x;
    if (i < HIDD) { g_bnsum[i] = 0.f; g_bnsq[i] = 0.f; }
}

// ---------------- CSR build ----------------
__global__ void k_deg(const int* __restrict__ dst) {
    int e = blockIdx.x * blockDim.x + threadIdx.x;
    if (e < EE) atomicAdd(&g_deg[dst[e]], 1);
}

__global__ void k_scan() {           // single block, 1024 threads: exclusive scan
    __shared__ int sh[1024];
    __shared__ int carry;
    int tid = threadIdx.x;
    if (tid == 0) { carry = 0; g_rowptr[0] = 0; }
    __syncthreads();
    for (int base = 0; base < NN; base += 1024) {
        int v = (base + tid < NN) ? g_deg[base + tid] : 0;
        sh[tid] = v;
        __syncthreads();
        for (int off = 1; off < 1024; off <<= 1) {
            int t = (tid >= off) ? sh[tid - off] : 0;
            __syncthreads();
            sh[tid] += t;
            __syncthreads();
        }
        if (base + tid < NN) g_rowptr[base + tid + 1] = carry + sh[tid];
        __syncthreads();
        if (tid == 0) carry += sh[1023];
        __syncthreads();
    }
}

__global__ void k_fill(const int* __restrict__ dst) {
    int e = blockIdx.x * blockDim.x + threadIdx.x;
    if (e < EE) {
        int d = dst[e];
        int p = atomicAdd(&g_fill[d], 1);
        g_col[g_rowptr[d] + p] = e;
    }
}

// ---------------- SGEMM: C[M,Nn] = A[M,K] @ B[K,Nn] (+bias) ----------------
// 64x64 tile, BK=16, 256 threads, 4x4 per-thread microtile.
__global__ void __launch_bounds__(256) k_sgemm(
    const float* __restrict__ A, const float* __restrict__ B,
    const float* __restrict__ bias, float* __restrict__ C,
    int M, int Nn, int K)
{
    __shared__ float As[16][64];
    __shared__ float Bs[16][64];
    int tid = threadIdx.x;
    int tx = tid & 15, ty = tid >> 4;
    int row0 = blockIdx.y * 64, col0 = blockIdx.x * 64;

    float acc[4][4];
#pragma unroll
    for (int i = 0; i < 4; i++)
#pragma unroll
        for (int j = 0; j < 4; j++) acc[i][j] = 0.f;

    int lr = tid >> 2;              // A load: row in tile
    int lk = (tid & 3) * 4;         // A load: k chunk
    int bk = tid >> 4;              // B load: k row
    int bn = (tid & 15) * 4;        // B load: n chunk

    for (int k0 = 0; k0 < K; k0 += 16) {
        float4 av = make_float4(0.f, 0.f, 0.f, 0.f);
        if (row0 + lr < M)
            av = *(const float4*)&A[(size_t)(row0 + lr) * K + k0 + lk];
        As[lk + 0][lr] = av.x; As[lk + 1][lr] = av.y;
        As[lk + 2][lr] = av.z; As[lk + 3][lr] = av.w;
        float4 bv = *(const float4*)&B[(size_t)(k0 + bk) * Nn + col0 + bn];
        *(float4*)&Bs[bk][bn] = bv;
        __syncthreads();
#pragma unroll
        for (int k = 0; k < 16; k++) {
            float4 a = *(float4*)&As[k][ty * 4];
            float4 b = *(float4*)&Bs[k][tx * 4];
            acc[0][0] += a.x * b.x; acc[0][1] += a.x * b.y; acc[0][2] += a.x * b.z; acc[0][3] += a.x * b.w;
            acc[1][0] += a.y * b.x; acc[1][1] += a.y * b.y; acc[1][2] += a.y * b.z; acc[1][3] += a.y * b.w;
            acc[2][0] += a.z * b.x; acc[2][1] += a.z * b.y; acc[2][2] += a.z * b.z; acc[2][3] += a.z * b.w;
            acc[3][0] += a.w * b.x; acc[3][1] += a.w * b.y; acc[3][2] += a.w * b.z; acc[3][3] += a.w * b.w;
        }
        __syncthreads();
    }

    float bv[4] = {0.f, 0.f, 0.f, 0.f};
    if (bias) {
#pragma unroll
        for (int j = 0; j < 4; j++) bv[j] = bias[col0 + tx * 4 + j];
    }
#pragma unroll
    for (int i = 0; i < 4; i++) {
        int r = row0 + ty * 4 + i;
        if (r < M) {
            float4 o;
            o.x = acc[i][0] + bv[0]; o.y = acc[i][1] + bv[1];
            o.z = acc[i][2] + bv[2]; o.w = acc[i][3] + bv[3];
            *(float4*)&C[(size_t)r * Nn + col0 + tx * 4] = o;
        }
    }
}

// ---------------- folded edge-attention weights ----------------
__global__ void k_ve(const float* __restrict__ We, const float* __restrict__ att_edge) {
    int t = blockIdx.x * blockDim.x + threadIdx.x;      // NL*128*4 = 1024
    if (t >= NL * HIDD * NH) return;
    int h = t & 3, k = (t >> 2) & 127, l = t >> 9;
    const float* w = We + (size_t)l * HIDD * (NH * HIDD) + (size_t)k * (NH * HIDD) + h * HIDD;
    const float* a = att_edge + (size_t)l * NH * HIDD + h * HIDD;
    float s = 0.f;
    for (int c = 0; c < HIDD; c++) s += w[c] * a[c];
    g_ve[t] = s;
}

__global__ void k_ue(const float* __restrict__ eenc_W, const float* __restrict__ eenc_b) {
    int t = blockIdx.x * blockDim.x + threadIdx.x;
    if (t < NL * 64 * NH) {
        int h = t & 3, j = (t >> 2) & 63, l = t >> 8;
        float s = 0.f;
        for (int k = 0; k < HIDD; k++) s += eenc_W[j * HIDD + k] * g_ve[l * 512 + k * 4 + h];
        g_ue[t] = s;
    } else if (t < NL * 64 * NH + NL * NH) {
        int q = t - NL * 64 * NH;
        int h = q & 3, l = q >> 2;
        float s = 0.f;
        for (int k = 0; k < HIDD; k++) s += eenc_b[k] * g_ve[l * 512 + k * 4 + h];
        g_ce[q] = s;
    }
}

// a_e[e, l, h] = edge_attr[e,:] @ u_e[l,:,h] + c_e[l,h]   (warp per edge)
__global__ void k_ae(const float* __restrict__ edge_attr) {
    __shared__ float su[NL * 64 * NH];
    __shared__ float sc[NL * NH];
    int tid = threadIdx.x;
    for (int i = tid; i < NL * 64 * NH; i += blockDim.x) su[i] = g_ue[i];
    if (tid < NL * NH) sc[tid] = g_ce[tid];
    __syncthreads();

    int lane = tid & 31;
    int warp = (blockIdx.x * blockDim.x + tid) >> 5;
    int nwarps = (gridDim.x * blockDim.x) >> 5;
    for (int e = warp; e < EE; e += nwarps) {
        float x1 = edge_attr[(size_t)e * 64 + lane];
        float x2 = edge_attr[(size_t)e * 64 + 32 + lane];
        float p[8];
#pragma unroll
        for (int o = 0; o < 8; o++) {
            int l = o >> 2, h = o & 3;
            p[o] = x1 * su[l * 256 + lane * 4 + h] + x2 * su[l * 256 + (32 + lane) * 4 + h];
        }
#pragma unroll
        for (int off = 16; off; off >>= 1)
#pragma unroll
            for (int o = 0; o < 8; o++) p[o] += __shfl_xor_sync(~0u, p[o], off);
        if (lane < 8) g_ae[(size_t)e * 8 + lane] = p[lane] + sc[lane];
    }
}

// self-loop logits: segment mean of a_e over incoming edges
__global__ void k_aeloop() {
    int t = blockIdx.x * blockDim.x + threadIdx.x;
    if (t < NN * 8) {
        int n = t >> 3, o = t & 7;
        int r0 = g_rowptr[n], r1 = g_rowptr[n + 1];
        float s = 0.f;
        for (int i = r0; i < r1; i++) s += g_ae[(size_t)g_col[i] * 8 + o];
        g_aeloop[t] = s / fmaxf((float)(r1 - r0), 1.f);
    }
}

// ---------------- per-node attention scalars ----------------
__global__ void k_attsd(const float* __restrict__ att_src, const float* __restrict__ att_dst) {
    int gt = blockIdx.x * blockDim.x + threadIdx.x;
    int w = gt >> 5, lane = gt & 31;
    int nw = (gridDim.x * blockDim.x) >> 5;
    for (int n = w; n < NN; n += nw) {
        const float4* xr = (const float4*)(g_xh + (size_t)n * 512);
        float ps = 0.f, pd = 0.f;
#pragma unroll
        for (int j = 0; j < 4; j++) {
            float4 v = xr[lane * 4 + j];
            float4 as = ((const float4*)att_src)[lane * 4 + j];
            float4 ad = ((const float4*)att_dst)[lane * 4 + j];
            ps += v.x * as.x + v.y * as.y + v.z * as.z + v.w * as.w;
            pd += v.x * ad.x + v.y * ad.y + v.z * ad.z + v.w * ad.w;
        }
#pragma unroll
        for (int off = 4; off; off >>= 1) {
            ps += __shfl_down_sync(~0u, ps, off);
            pd += __shfl_down_sync(~0u, pd, off);
        }
        if ((lane & 7) == 0) {
            g_asrc[n * 4 + (lane >> 3)] = ps;
            g_adst[n * 4 + (lane >> 3)] = pd;
        }
    }
}

// ---------------- fused softmax + aggregation, one block (128 thr) per dst node ----------------
__global__ void __launch_bounds__(128) k_agg(const int* __restrict__ srcArr,
                                             const float* __restrict__ bias, int l) {
    __shared__ float wbuf[512];
    __shared__ int   sbuf[128];
    __shared__ float sred[16];

    int n = blockIdx.x;
    int tid = threadIdx.x, lane = tid & 31, wid = tid >> 5;
    int row = g_rowptr[n];
    int deg = g_rowptr[n + 1] - row;

    float ad[4], aself[4], m[4];
#pragma unroll
    for (int h = 0; h < 4; h++) ad[h] = g_adst[n * 4 + h];
#pragma unroll
    for (int h = 0; h < 4; h++) {
        float a = g_asrc[n * 4 + h] + ad[h] + g_aeloop[n * 8 + l * 4 + h];
        aself[h] = (a >= 0.f) ? a : NEG * a;
        m[h] = aself[h];
    }

    // pass 1: block max of leaky-relu logits
    for (int i = tid; i < deg; i += 128) {
        int e = g_col[row + i];
        int s = srcArr[e];
#pragma unroll
        for (int h = 0; h < 4; h++) {
            float a = g_asrc[s * 4 + h] + ad[h] + g_ae[(size_t)e * 8 + l * 4 + h];
            a = (a >= 0.f) ? a : NEG * a;
            m[h] = fmaxf(m[h], a);
        }
    }
#pragma unroll
    for (int h = 0; h < 4; h++)
#pragma unroll
        for (int off = 16; off; off >>= 1) m[h] = fmaxf(m[h], __shfl_xor_sync(~0u, m[h], off));
    if (lane == 0) {
#pragma unroll
        for (int h = 0; h < 4; h++) sred[wid * 4 + h] = m[h];
    }
    __syncthreads();
#pragma unroll
    for (int h = 0; h < 4; h++)
        m[h] = fmaxf(fmaxf(sred[h], sred[4 + h]), fmaxf(sred[8 + h], sred[12 + h]));
    __syncthreads();

    // pass 2: chunked exp + weighted feature gather
    float4 acc = make_float4(0.f, 0.f, 0.f, 0.f);
    float sw[4] = {0.f, 0.f, 0.f, 0.f};
    for (int base = 0; base < deg; base += 128) {
        int i = base + tid;
        if (i < deg) {
            int e = g_col[row + i];
            int s = srcArr[e];
            sbuf[tid] = s;
#pragma unroll
            for (int h = 0; h < 4; h++) {
                float a = g_asrc[s * 4 + h] + ad[h] + g_ae[(size_t)e * 8 + l * 4 + h];
                a = (a >= 0.f) ? a : NEG * a;
                float ww = __expf(a - m[h]);
                wbuf[tid * 4 + h] = ww;
                sw[h] += ww;
            }
        }
        __syncthreads();
        int cnt = min(128, deg - base);
        for (int j = 0; j < cnt; j++) {
            int s = sbuf[j];
            float4 xv = *(const float4*)(g_xh + (size_t)s * 512 + tid * 4);
            float ww = wbuf[j * 4 + wid];
            acc.x += ww * xv.x; acc.y += ww * xv.y;
            acc.z += ww * xv.z; acc.w += ww * xv.w;
        }
        __syncthreads();
    }

    // reduce sum-of-weights
#pragma unroll
    for (int h = 0; h < 4; h++)
#pragma unroll
        for (int off = 16; off; off >>= 1) sw[h] += __shfl_xor_sync(~0u, sw[h], off);
    if (lane == 0) {
#pragma unroll
        for (int h = 0; h < 4; h++) sred[wid * 4 + h] = sw[h];
    }
    __syncthreads();
    float denom[4], wself[4];
#pragma unroll
    for (int h = 0; h < 4; h++) {
        wself[h] = __expf(aself[h] - m[h]);
        denom[h] = sred[h] + sred[4 + h] + sred[8 + h] + sred[12 + h] + wself[h] + 1e-16f;
    }
    // self-loop message
    float4 xs = *(const float4*)(g_xh + (size_t)n * 512 + tid * 4);
    acc.x += wself[wid] * xs.x; acc.y += wself[wid] * xs.y;
    acc.z += wself[wid] * xs.z; acc.w += wself[wid] * xs.w;

    float inv = 1.f / denom[wid];
    acc.x *= inv; acc.y *= inv; acc.z *= inv; acc.w *= inv;

    __syncthreads();
    ((float4*)wbuf)[tid] = acc;
    __syncthreads();
    if (tid < 32) {
#pragma unroll
        for (int k = 0; k < 4; k++) {
            float s = wbuf[tid * 4 + k] + wbuf[(32 + tid) * 4 + k] +
                      wbuf[(64 + tid) * 4 + k] + wbuf[(96 + tid) * 4 + k];
            g_outp[n * 128 + tid * 4 + k] = 0.25f * s + bias[tid * 4 + k];
        }
    }
}

// ---------------- batchnorm ----------------
__global__ void k_bnreduce() {
    int c = threadIdx.x;    // 128 threads/block
    int rows_per = (NN + gridDim.x - 1) / gridDim.x;
    int r0 = blockIdx.x * rows_per;
    int r1 = min(NN, r0 + rows_per);
    float s = 0.f, q = 0.f;
    for (int r = r0; r < r1; r++) {
        float v = g_outp[r * 128 + c];
        s += v; q += v * v;
    }
    atomicAdd(&g_bnsum[c], s);
    atomicAdd(&g_bnsq[c], q);
}

__global__ void k_bnapply(const float* __restrict__ gamma, const float* __restrict__ beta,
                          float* __restrict__ out, int writeOut) {
    int i = blockIdx.x * blockDim.x + threadIdx.x;
    if (i < NN * 128) {
        int c = i & 127;
        float mu = g_bnsum[c] * (1.f / NN);
        float var = g_bnsq[c] * (1.f / NN) - mu * mu;
        float v = (g_outp[i] - mu) * rsqrtf(var + BNEPS) * gamma[c] + beta[c];
        float r = fmaxf(v, 0.f) + g_h[i];
        g_h[i] = r;
        if (writeOut) out[i] = r;
    }
}

// ---------------- launch ----------------
extern "C" void kernel_launch(void* const* d_in, const int* in_sizes, int n_in,
                              void* d_out, int out_size) {
    (void)in_sizes; (void)n_in; (void)out_size;
    const float* x        = (const float*)d_in[0];
    const int*   ei       = (const int*)d_in[1];
    const float* eattr    = (const float*)d_in[2];
    const float* encW     = (const float*)d_in[4];
    const float* encb     = (const float*)d_in[5];
    const float* eencW    = (const float*)d_in[6];
    const float* eencb    = (const float*)d_in[7];
    const float* W        = (const float*)d_in[8];
    const float* We       = (const float*)d_in[9];
    const float* att_src  = (const float*)d_in[10];
    const float* att_dst  = (const float*)d_in[11];
    const float* att_edge = (const float*)d_in[12];
    const float* bias     = (const float*)d_in[13];
    const float* gamma    = (const float*)d_in[14];
    const float* beta     = (const float*)d_in[15];
    const int* src = ei;
    const int* dst = ei + EE;

    float *p_h, *p_xh;
    cudaGetSymbolAddress((void**)&p_h, g_h);
    cudaGetSymbolAddress((void**)&p_xh, g_xh);

    // CSR build
    k_zero_counts<<<(NN + 255) / 256, 256>>>();
    k_deg<<<(EE + 255) / 256, 256>>>(dst);
    k_scan<<<1, 1024>>>();
    k_fill<<<(EE + 255) / 256, 256>>>(dst);

    // node encoder: h = x @ enc_W + enc_b
    k_sgemm<<<dim3(128 / 64, (NN + 63) / 64), 256>>>(x, encW, encb, p_h, NN, 128, 128);

    // folded edge attention logits for both layers
    k_ve<<<(NL * HIDD * NH + 255) / 256, 256>>>(We, att_edge);
    k_ue<<<(NL * 64 * NH + NL * NH + 255) / 256, 256>>>(eencW, eencb);
    k_ae<<<1024, 256>>>(eattr);
    k_aeloop<<<(NN * 8 + 255) / 256, 256>>>();

    for (int l = 0; l < NL; l++) {
        k_sgemm<<<dim3(512 / 64, (NN + 63) / 64), 256>>>(
            p_h, W + (size_t)l * HIDD * (NH * HIDD), nullptr, p_xh, NN, NH * HIDD, HIDD);
        k_attsd<<<160, 256>>>(att_src + l * NH * HIDD, att_dst + l * NH * HIDD);
        k_agg<<<NN, 128>>>(src, bias + l * HIDD, l);
        k_bnzero<<<1, 128>>>();
        k_bnreduce<<<80, 128>>>();
        k_bnapply<<<(NN * 128 + 255) / 256, 256>>>(
            gamma + l * HIDD, beta + l * HIDD, (float*)d_out, (l == NL - 1) ? 1 : 0);
    }
}

// round 10
// speedup vs baseline: 1.1059x; 1.1059x over previous
#include <cuda_runtime.h>
#include <stdint.h>
#include <math.h>

#define NN   10000
#define EE   320000
#define HIDD 128
#define NH   4
#define NL   2
#define NEG  0.2f
#define BNEPS 1e-5f

// ---------------- scratch ----------------
__device__ float g_h[NN * HIDD];
__device__ float g_xh[NN * HIDD * NH];
__device__ float g_outp[NN * HIDD];
__device__ float g_ae[EE * 8];              // [E][L][H]
__device__ float g_aeloop[NN * 8];
__device__ float g_asrc[NN * NH];
__device__ float g_adst[NN * NH];
__device__ int   g_deg[NN];
__device__ int   g_rowptr[NN + 1];
__device__ int   g_fill[NN];
__device__ int   g_col[EE];
__device__ float g_ve[NL * HIDD * NH];      // We . att_edge
__device__ float g_ue[NL * 64 * NH];        // eenc_W @ ve
__device__ float g_ce[NL * NH];
__device__ float g_wsd[NL * HIDD * 8];      // W . att_src / att_dst  [L][128][8]
__device__ float g_bnsum[HIDD];
__device__ float g_bnsq[HIDD];

// ---------------- tf32 helpers ----------------
__device__ __forceinline__ uint32_t f2tf32(float f) {
    uint32_t u; asm("cvt.rna.tf32.f32 %0, %1;" : "=r"(u) : "f"(f)); return u;
}
__device__ __forceinline__ void mma8(float* c, const uint32_t* a, uint32_t b0, uint32_t b1) {
    asm("mma.sync.aligned.m16n8k8.row.col.f32.tf32.tf32.f32 "
        "{%0,%1,%2,%3},{%4,%5,%6,%7},{%8,%9},{%0,%1,%2,%3};"
        : "+f"(c[0]), "+f"(c[1]), "+f"(c[2]), "+f"(c[3])
        : "r"(a[0]), "r"(a[1]), "r"(a[2]), "r"(a[3]), "r"(b0), "r"(b1));
}

// ---------------- init ----------------
__global__ void k_zero_counts() {
    int i = blockIdx.x * blockDim.x + threadIdx.x;
    if (i < NN) { g_deg[i] = 0; g_fill[i] = 0; }
}
__global__ void k_bnzero() {
    int i = threadIdx.x;
    if (i < HIDD) { g_bnsum[i] = 0.f; g_bnsq[i] = 0.f; }
}

// ---------------- CSR ----------------
__global__ void k_deg(const int* __restrict__ dst) {
    int e = blockIdx.x * blockDim.x + threadIdx.x;
    if (e < EE) atomicAdd(&g_deg[dst[e]], 1);
}

__global__ void k_scan() {   // 1 block, 1024 threads, warp-shuffle scan
    __shared__ int wsum[32];
    __shared__ int carry;
    int tid = threadIdx.x, lane = tid & 31, wid = tid >> 5;
    if (tid == 0) { carry = 0; g_rowptr[0] = 0; }
    __syncthreads();
    for (int base = 0; base < NN; base += 1024) {
        int v = (base + tid < NN) ? g_deg[base + tid] : 0;
        int s = v;
#pragma unroll
        for (int off = 1; off < 32; off <<= 1) {
            int t = __shfl_up_sync(~0u, s, off);
            if (lane >= off) s += t;
        }
        if (lane == 31) wsum[wid] = s;
        __syncthreads();
        if (wid == 0) {
            int ws = wsum[lane];
#pragma unroll
            for (int off = 1; off < 32; off <<= 1) {
                int t = __shfl_up_sync(~0u, ws, off);
                if (lane >= off) ws += t;
            }
            wsum[lane] = ws;
        }
        __syncthreads();
        int add = carry + (wid ? wsum[wid - 1] : 0);
        if (base + tid < NN) g_rowptr[base + tid + 1] = add + s;
        __syncthreads();
        if (tid == 0) carry += wsum[31];
        __syncthreads();
    }
}

__global__ void k_fill(const int* __restrict__ dst) {
    int e = blockIdx.x * blockDim.x + threadIdx.x;
    if (e < EE) {
        int d = dst[e];
        int p = atomicAdd(&g_fill[d], 1);
        g_col[g_rowptr[d] + p] = e;
    }
}

// ---------------- 3xTF32 tensor-core GEMM: C[M,Nn] = A[M,128] @ B[128,Nn] (+bias) ----------------
// BM=128, BN=64, BK=32, 256 threads (8 warps, 4x2), warp tile 32x32.
__global__ void __launch_bounds__(256) k_gemm_tf32(
    const float* __restrict__ A, const float* __restrict__ B,
    const float* __restrict__ bias, float* __restrict__ C,
    int M, int Nn)
{
    __shared__ float Ah[32][136];
    __shared__ float Al[32][136];
    __shared__ float Bs[32][72];

    int tid = threadIdx.x;
    int warp = tid >> 5, lane = tid & 31;
    int wm = warp & 3, wn = warp >> 2;
    int m0 = wm * 32, n0 = wn * 32;
    int row0 = blockIdx.y * 128, col0 = blockIdx.x * 64;

    float acc[2][4][4];
#pragma unroll
    for (int a = 0; a < 2; a++)
#pragma unroll
        for (int b = 0; b < 4; b++)
#pragma unroll
            for (int c = 0; c < 4; c++) acc[a][b][c] = 0.f;

    int fr = lane >> 2, fc = lane & 3;

    for (int kt = 0; kt < 128; kt += 32) {
        // A tile: r = tid&127, transposed split store
        int r = tid & 127;
        int gr = row0 + r;
#pragma unroll
        for (int i = 0; i < 4; i++) {
            int c4 = (tid >> 7) + 2 * i;
            float4 v = make_float4(0.f, 0.f, 0.f, 0.f);
            if (gr < M) v = *(const float4*)&A[(size_t)gr * 128 + kt + c4 * 4];
            const float* vp = &v.x;
#pragma unroll
            for (int j = 0; j < 4; j++) {
                float f = vp[j];
                uint32_t hb = f2tf32(f);
                float hf = __uint_as_float(hb);
                Ah[c4 * 4 + j][r] = hf;
                Al[c4 * 4 + j][r] = __uint_as_float(f2tf32(f - hf));
            }
        }
        // B tile
#pragma unroll
        for (int i = 0; i < 2; i++) {
            int kk = (tid >> 4) + 16 * i;
            float4 v = *(const float4*)&B[(size_t)(kt + kk) * Nn + col0 + (tid & 15) * 4];
            *(float4*)&Bs[kk][(tid & 15) * 4] = v;
        }
        __syncthreads();

#pragma unroll
        for (int ks = 0; ks < 4; ks++) {
            int kb = ks * 8;
            uint32_t ah[2][4], al[2][4];
#pragma unroll
            for (int mi = 0; mi < 2; mi++) {
                int mr = m0 + mi * 16;
                ah[mi][0] = __float_as_uint(Ah[kb + fc][mr + fr]);
                ah[mi][1] = __float_as_uint(Ah[kb + fc][mr + fr + 8]);
                ah[mi][2] = __float_as_uint(Ah[kb + fc + 4][mr + fr]);
                ah[mi][3] = __float_as_uint(Ah[kb + fc + 4][mr + fr + 8]);
                al[mi][0] = __float_as_uint(Al[kb + fc][mr + fr]);
                al[mi][1] = __float_as_uint(Al[kb + fc][mr + fr + 8]);
                al[mi][2] = __float_as_uint(Al[kb + fc + 4][mr + fr]);
                al[mi][3] = __float_as_uint(Al[kb + fc + 4][mr + fr + 8]);
            }
#pragma unroll
            for (int ni = 0; ni < 4; ni++) {
                int nc = n0 + ni * 8 + (lane >> 2);
                float b0f = Bs[kb + fc][nc];
                float b1f = Bs[kb + fc + 4][nc];
                uint32_t b0h = f2tf32(b0f);
                uint32_t b1h = f2tf32(b1f);
                uint32_t b0l = f2tf32(b0f - __uint_as_float(b0h));
                uint32_t b1l = f2tf32(b1f - __uint_as_float(b1h));
#pragma unroll
                for (int mi = 0; mi < 2; mi++) {
                    mma8(acc[mi][ni], ah[mi], b0l, b1l);
                    mma8(acc[mi][ni], al[mi], b0h, b1h);
                    mma8(acc[mi][ni], ah[mi], b0h, b1h);
                }
            }
        }
        __syncthreads();
    }

    // epilogue
#pragma unroll
    for (int mi = 0; mi < 2; mi++) {
#pragma unroll
        for (int ni = 0; ni < 4; ni++) {
            int cc0 = col0 + n0 + ni * 8 + (lane & 3) * 2;
            float bb0 = 0.f, bb1 = 0.f;
            if (bias) { bb0 = bias[cc0]; bb1 = bias[cc0 + 1]; }
            int rr = row0 + m0 + mi * 16 + (lane >> 2);
            if (rr < M) {
                float2 o = make_float2(acc[mi][ni][0] + bb0, acc[mi][ni][1] + bb1);
                *(float2*)&C[(size_t)rr * Nn + cc0] = o;
            }
            if (rr + 8 < M) {
                float2 o = make_float2(acc[mi][ni][2] + bb0, acc[mi][ni][3] + bb1);
                *(float2*)&C[(size_t)(rr + 8) * Nn + cc0] = o;
            }
        }
    }
}

// ---------------- folded attention weights ----------------
__global__ void k_ve(const float* __restrict__ We, const float* __restrict__ att_edge) {
    int t = blockIdx.x * blockDim.x + threadIdx.x;
    if (t >= NL * HIDD * NH) return;
    int h = t & 3, k = (t >> 2) & 127, l = t >> 9;
    const float* w = We + (size_t)l * HIDD * (NH * HIDD) + (size_t)k * (NH * HIDD) + h * HIDD;
    const float* a = att_edge + (size_t)l * NH * HIDD + h * HIDD;
    float s = 0.f;
    for (int c = 0; c < HIDD; c++) s += w[c] * a[c];
    g_ve[t] = s;
}

__global__ void k_ue(const float* __restrict__ eenc_W, const float* __restrict__ eenc_b) {
    int t = blockIdx.x * blockDim.x + threadIdx.x;
    if (t < NL * 64 * NH) {
        int h = t & 3, j = (t >> 2) & 63, l = t >> 8;
        float s = 0.f;
        for (int k = 0; k < HIDD; k++) s += eenc_W[j * HIDD + k] * g_ve[l * 512 + k * 4 + h];
        g_ue[t] = s;
    } else if (t < NL * 64 * NH + NL * NH) {
        int q = t - NL * 64 * NH;
        int h = q & 3, l = q >> 2;
        float s = 0.f;
        for (int k = 0; k < HIDD; k++) s += eenc_b[k] * g_ve[l * 512 + k * 4 + h];
        g_ce[q] = s;
    }
}

__global__ void k_wsd(const float* __restrict__ W, const float* __restrict__ att_src,
                      const float* __restrict__ att_dst) {
    int t = blockIdx.x * blockDim.x + threadIdx.x;
    if (t >= NL * HIDD * 8) return;
    int o = t & 7, k = (t >> 3) & 127, l = t >> 10;
    int h = o & 3;
    const float* a = ((o < 4) ? att_src : att_dst) + ((size_t)l * 4 + h) * HIDD;
    const float* w = W + ((size_t)l * HIDD + k) * (NH * HIDD) + h * HIDD;
    float s = 0.f;
    for (int c = 0; c < HIDD; c++) s += w[c] * a[c];
    g_wsd[((size_t)l * HIDD + k) * 8 + o] = s;
}

// edge logits: 4 edges/warp, 8 lanes each, weights register-resident
__global__ void __launch_bounds__(256) k_ae(const float* __restrict__ edge_attr) {
    int lane = threadIdx.x & 31;
    int kb = (lane & 7) * 8;
    float uw[8][8];
#pragma unroll
    for (int i = 0; i < 8; i++)
#pragma unroll
        for (int o = 0; o < 8; o++)
            uw[i][o] = g_ue[(o >> 2) * 256 + (kb + i) * 4 + (o & 3)];
    float cst = g_ce[lane & 7];

    int sub = lane >> 3;
    int warp = (blockIdx.x * blockDim.x + threadIdx.x) >> 5;
    int nw = (gridDim.x * blockDim.x) >> 5;
    for (int e4 = warp; e4 < EE / 4; e4 += nw) {
        int e = e4 * 4 + sub;
        float4 v0 = *(const float4*)&edge_attr[(size_t)e * 64 + kb];
        float4 v1 = *(const float4*)&edge_attr[(size_t)e * 64 + kb + 4];
        float p[8];
#pragma unroll
        for (int o = 0; o < 8; o++) {
            p[o] = v0.x * uw[0][o] + v0.y * uw[1][o] + v0.z * uw[2][o] + v0.w * uw[3][o]
                 + v1.x * uw[4][o] + v1.y * uw[5][o] + v1.z * uw[6][o] + v1.w * uw[7][o];
        }
#pragma unroll
        for (int off = 4; off; off >>= 1)
#pragma unroll
            for (int o = 0; o < 8; o++) p[o] += __shfl_xor_sync(~0u, p[o], off);
        g_ae[(size_t)e * 8 + (lane & 7)] = p[lane & 7] + cst;
    }
}

__global__ void k_aeloop() {
    int t = blockIdx.x * blockDim.x + threadIdx.x;
    if (t < NN * 8) {
        int n = t >> 3, o = t & 7;
        int r0 = g_rowptr[n], r1 = g_rowptr[n + 1];
        float s = 0.f;
        for (int i = r0; i < r1; i++) s += g_ae[(size_t)g_col[i] * 8 + o];
        g_aeloop[t] = s / fmaxf((float)(r1 - r0), 1.f);
    }
}

// a_src / a_dst = h @ g_wsd[l]   (warp per node)
__global__ void k_asd(int l) {
    int lane = threadIdx.x & 31;
    float wv[4][8];
#pragma unroll
    for (int j = 0; j < 4; j++)
#pragma unroll
        for (int o = 0; o < 8; o++)
            wv[j][o] = g_wsd[((size_t)l * HIDD + lane + 32 * j) * 8 + o];

    int warp = (blockIdx.x * blockDim.x + threadIdx.x) >> 5;
    int nw = (gridDim.x * blockDim.x) >> 5;
    for (int n = warp; n < NN; n += nw) {
        float p[8] = {0.f, 0.f, 0.f, 0.f, 0.f, 0.f, 0.f, 0.f};
#pragma unroll
        for (int j = 0; j < 4; j++) {
            float hv = g_h[(size_t)n * HIDD + lane + 32 * j];
#pragma unroll
            for (int o = 0; o < 8; o++) p[o] += hv * wv[j][o];
        }
#pragma unroll
        for (int off = 16; off; off >>= 1)
#pragma unroll
            for (int o = 0; o < 8; o++) p[o] += __shfl_xor_sync(~0u, p[o], off);
        if (lane < 4) g_asrc[n * 4 + lane] = p[lane];
        else if (lane < 8) g_adst[n * 4 + (lane - 4)] = p[lane];
    }
}

// ---------------- fused softmax + aggregation (no max pass) ----------------
__global__ void __launch_bounds__(128) k_agg(const int* __restrict__ srcArr,
                                             const float* __restrict__ bias, int l) {
    __shared__ float wbuf[512];
    __shared__ int   sbuf[128];
    __shared__ float sred[16];

    int n = blockIdx.x;
    int tid = threadIdx.x, lane = tid & 31, wid = tid >> 5;
    int row = g_rowptr[n];
    int deg = g_rowptr[n + 1] - row;

    float ad[4], wself[4];
#pragma unroll
    for (int h = 0; h < 4; h++) ad[h] = g_adst[n * 4 + h];
#pragma unroll
    for (int h = 0; h < 4; h++) {
        float a = g_asrc[n * 4 + h] + ad[h] + g_aeloop[n * 8 + l * 4 + h];
        a = (a >= 0.f) ? a : NEG * a;
        wself[h] = __expf(a);
    }

    float4 acc = make_float4(0.f, 0.f, 0.f, 0.f);
    float sw[4] = {0.f, 0.f, 0.f, 0.f};
    for (int base = 0; base < deg; base += 128) {
        int i = base + tid;
        if (i < deg) {
            int e = g_col[row + i];
            int s = srcArr[e];
            sbuf[tid] = s;
#pragma unroll
            for (int h = 0; h < 4; h++) {
                float a = g_asrc[s * 4 + h] + ad[h] + g_ae[(size_t)e * 8 + l * 4 + h];
                a = (a >= 0.f) ? a : NEG * a;
                float ww = __expf(a);
                wbuf[tid * 4 + h] = ww;
                sw[h] += ww;
            }
        }
        __syncthreads();
        int cnt = min(128, deg - base);
        for (int j = 0; j < cnt; j++) {
            int s = sbuf[j];
            float4 xv = *(const float4*)(g_xh + (size_t)s * 512 + tid * 4);
            float ww = wbuf[j * 4 + wid];
            acc.x += ww * xv.x; acc.y += ww * xv.y;
            acc.z += ww * xv.z; acc.w += ww * xv.w;
        }
        __syncthreads();
    }

#pragma unroll
    for (int h = 0; h < 4; h++)
#pragma unroll
        for (int off = 16; off; off >>= 1) sw[h] += __shfl_xor_sync(~0u, sw[h], off);
    if (lane == 0) {
#pragma unroll
        for (int h = 0; h < 4; h++) sred[wid * 4 + h] = sw[h];
    }
    __syncthreads();
    float denom[4];
#pragma unroll
    for (int h = 0; h < 4; h++)
        denom[h] = sred[h] + sred[4 + h] + sred[8 + h] + sred[12 + h] + wself[h] + 1e-16f;

    float4 xs = *(const float4*)(g_xh + (size_t)n * 512 + tid * 4);
    acc.x += wself[wid] * xs.x; acc.y += wself[wid] * xs.y;
    acc.z += wself[wid] * xs.z; acc.w += wself[wid] * xs.w;

    float inv = 1.f / denom[wid];
    acc.x *= inv; acc.y *= inv; acc.z *= inv; acc.w *= inv;

    __syncthreads();
    ((float4*)wbuf)[tid] = acc;
    __syncthreads();
    if (tid < 32) {
#pragma unroll
        for (int k = 0; k < 4; k++) {
            float s = wbuf[tid * 4 + k] + wbuf[(32 + tid) * 4 + k] +
                      wbuf[(64 + tid) * 4 + k] + wbuf[(96 + tid) * 4 + k];
            g_outp[n * 128 + tid * 4 + k] = 0.25f * s + bias[tid * 4 + k];
        }
    }
}

// ---------------- batchnorm ----------------
__global__ void k_bnreduce() {
    int c = threadIdx.x;
    int rows_per = (NN + gridDim.x - 1) / gridDim.x;
    int r0 = blockIdx.x * rows_per;
    int r1 = min(NN, r0 + rows_per);
    float s = 0.f, q = 0.f;
    for (int r = r0; r < r1; r++) {
        float v = g_outp[r * 128 + c];
        s += v; q += v * v;
    }
    atomicAdd(&g_bnsum[c], s);
    atomicAdd(&g_bnsq[c], q);
}

__global__ void k_bnapply(const float* __restrict__ gamma, const float* __restrict__ beta,
                          float* __restrict__ out, int writeOut) {
    int i = blockIdx.x * blockDim.x + threadIdx.x;
    if (i < NN * 128) {
        int c = i & 127;
        float mu = g_bnsum[c] * (1.f / NN);
        float var = g_bnsq[c] * (1.f / NN) - mu * mu;
        float v = (g_outp[i] - mu) * rsqrtf(var + BNEPS) * gamma[c] + beta[c];
        float r = fmaxf(v, 0.f) + g_h[i];
        g_h[i] = r;
        if (writeOut) out[i] = r;
    }
}

// ---------------- launch ----------------
extern "C" void kernel_launch(void* const* d_in, const int* in_sizes, int n_in,
                              void* d_out, int out_size) {
    (void)in_sizes; (void)n_in; (void)out_size;
    const float* x        = (const float*)d_in[0];
    const int*   ei       = (const int*)d_in[1];
    const float* eattr    = (const float*)d_in[2];
    const float* encW     = (const float*)d_in[4];
    const float* encb     = (const float*)d_in[5];
    const float* eencW    = (const float*)d_in[6];
    const float* eencb    = (const float*)d_in[7];
    const float* W        = (const float*)d_in[8];
    const float* We       = (const float*)d_in[9];
    const float* att_src  = (const float*)d_in[10];
    const float* att_dst  = (const float*)d_in[11];
    const float* att_edge = (const float*)d_in[12];
    const float* bias     = (const float*)d_in[13];
    const float* gamma    = (const float*)d_in[14];
    const float* beta     = (const float*)d_in[15];
    const int* src = ei;
    const int* dst = ei + EE;

    float *p_h, *p_xh;
    cudaGetSymbolAddress((void**)&p_h, g_h);
    cudaGetSymbolAddress((void**)&p_xh, g_xh);

    // CSR
    k_zero_counts<<<(NN + 255) / 256, 256>>>();
    k_deg<<<(EE + 255) / 256, 256>>>(dst);
    k_scan<<<1, 1024>>>();
    k_fill<<<(EE + 255) / 256, 256>>>(dst);

    // folded weights
    k_ve<<<(NL * HIDD * NH + 255) / 256, 256>>>(We, att_edge);
    k_ue<<<(NL * 64 * NH + NL * NH + 255) / 256, 256>>>(eencW, eencb);
    k_wsd<<<(NL * HIDD * 8 + 255) / 256, 256>>>(W, att_src, att_dst);

    // edge logits (both layers) + self-loop means
    k_ae<<<1024, 256>>>(eattr);
    k_aeloop<<<(NN * 8 + 255) / 256, 256>>>();

    // encoder
    k_gemm_tf32<<<dim3(2, (NN + 127) / 128), 256>>>(x, encW, encb, p_h, NN, 128);

    for (int l = 0; l < NL; l++) {
        k_gemm_tf32<<<dim3(8, (NN + 127) / 128), 256>>>(
            p_h, W + (size_t)l * HIDD * (NH * HIDD), nullptr, p_xh, NN, 512);
        k_asd<<<160, 256>>>(l);
        k_agg<<<NN, 128>>>(src, bias + l * HIDD, l);
        k_bnzero<<<1, 128>>>();
        k_bnreduce<<<80, 128>>>();
        k_bnapply<<<(NN * 128 + 255) / 256, 256>>>(
            gamma + l * HIDD, beta + l * HIDD, (float*)d_out, (l == NL - 1) ? 1 : 0);
    }
}